// round 8
// baseline (speedup 1.0000x reference)
#include <cuda_runtime.h>
#include <cstdint>

#define B_SZ 512
#define D_SZ 1024
#define P_SZ 16
#define N_SZ 128
#define ALPHA_F 0.8f
#define NROWS 145                 // row 0 = tgt, 1..16 = rel, 17..144 = irr
#define SPLIT 8
#define NBLOCKS (B_SZ * SPLIT)    // 4096
#define TPB 128
#define NWARPS 4
#define DEPTH 3                   // stages per warp
#define STAGE_BYTES 2048          // half row (512 fp32)

// dynamic smem: [buffers: NWARPS*DEPTH*STAGE_BYTES][mbarriers: NWARPS*DEPTH*8]
#define SMEM_BUF_BYTES (NWARPS * DEPTH * STAGE_BYTES)   // 24576
#define SMEM_TOTAL     (SMEM_BUF_BYTES + NWARPS * DEPTH * 8 + 16)

__device__ float g_pos[NBLOCKS];
__device__ float g_neg[NBLOCKS];
__device__ float g_diag[B_SZ];
__device__ unsigned int g_count = 0;

__device__ __forceinline__ uint32_t smem_u32(const void* p) {
    uint32_t a;
    asm("{ .reg .u64 t; cvta.to.shared.u64 t, %1; cvt.u32.u64 %0, t; }"
        : "=r"(a) : "l"(p));
    return a;
}
__device__ __forceinline__ void mbar_init(uint32_t mbar, uint32_t count) {
    asm volatile("mbarrier.init.shared.b64 [%0], %1;" :: "r"(mbar), "r"(count) : "memory");
}
__device__ __forceinline__ void mbar_expect_tx(uint32_t mbar, uint32_t bytes) {
    asm volatile("mbarrier.arrive.expect_tx.shared.b64 _, [%0], %1;"
                 :: "r"(mbar), "r"(bytes) : "memory");
}
__device__ __forceinline__ void tma_half(uint32_t smem_dst, const float* gmem_src, uint32_t mbar) {
    asm volatile("cp.async.bulk.shared::cta.global.mbarrier::complete_tx::bytes "
                 "[%0], [%1], %2, [%3];"
                 :: "r"(smem_dst), "l"(gmem_src), "r"((uint32_t)STAGE_BYTES), "r"(mbar)
                 : "memory");
}
__device__ __forceinline__ void mbar_wait(uint32_t mbar, uint32_t parity) {
    uint32_t done;
    asm volatile(
        "{\n\t.reg .pred p;\n\t"
        "mbarrier.try_wait.parity.acquire.cta.shared::cta.b64 p, [%1], %2;\n\t"
        "selp.b32 %0, 1, 0, p;\n\t}"
        : "=r"(done) : "r"(mbar), "r"(parity) : "memory");
    if (!done) {
        asm volatile(
            "{\n\t.reg .pred P1;\n\t"
            "W_%=:\n\t"
            "mbarrier.try_wait.parity.acquire.cta.shared::cta.b64 P1, [%0], %1, 0x989680;\n\t"
            "@P1 bra.uni D_%=;\n\t"
            "bra.uni W_%=;\n\t"
            "D_%=:\n\t}"
            :: "r"(mbar), "r"(parity) : "memory");
    }
}

__device__ __forceinline__ const float*
row_ptr(const float* __restrict__ tgt, const float* __restrict__ rel,
        const float* __restrict__ irr, int b, int r)
{
    if (r == 0)         return tgt + (size_t)b * D_SZ;
    else if (r <= P_SZ) return rel + ((size_t)b * P_SZ + (r - 1)) * D_SZ;
    else                return irr + ((size_t)b * N_SZ + (r - 1 - P_SZ)) * D_SZ;
}

__global__ void __launch_bounds__(TPB)
contrastive_loss_kernel(const float* __restrict__ src,
                        const float* __restrict__ tgt,
                        const float* __restrict__ rel,
                        const float* __restrict__ irr,
                        float* __restrict__ out)
{
    extern __shared__ __align__(16) char dsm[];
    __shared__ float s_pos[NWARPS], s_neg[NWARPS];
    __shared__ int   s_last;

    const int blk  = blockIdx.x;
    const int b    = blk >> 3;            // batch row
    const int s    = blk & 7;             // split index
    const int tid  = threadIdx.x;
    const int wid  = tid >> 5;
    const int lane = tid & 31;

    const uint32_t dsm_base  = smem_u32(dsm);
    const uint32_t my_buf0   = dsm_base + (uint32_t)(wid * DEPTH) * STAGE_BYTES;
    const uint32_t my_mbar0  = dsm_base + SMEM_BUF_BYTES + (uint32_t)(wid * DEPTH) * 8;

    if (lane == 0) {
        #pragma unroll
        for (int k = 0; k < DEPTH; k++) mbar_init(my_mbar0 + k * 8, 1);
        asm volatile("fence.mbarrier_init.release.cluster;" ::: "memory");
    }
    __syncwarp();

    // ---- rows for this warp: first, first+4, ... (stride interleave, R6-style) ----
    const int r0 = (s * NROWS) / SPLIT;
    const int r1 = ((s + 1) * NROWS) / SPLIT;
    const int first = r0 + wid;
    const int nr = (first < r1) ? ((r1 - first + NWARPS - 1) / NWARPS) : 0;
    const int nh = nr * 2;                 // half-row work items

    // half hi -> row (first + (hi>>1)*4), byte offset (hi&1)*2048
    // stage k = hi % 3, parity = (hi/3) & 1

    // ---- prime pipeline (3 halves) before src load ----
    if (lane == 0) {
        #pragma unroll
        for (int k = 0; k < DEPTH; k++) {
            if (k < nh) {
                const float* p = row_ptr(tgt, rel, irr, b, first + (k >> 1) * NWARPS)
                                 + (k & 1) * (STAGE_BYTES / 4);
                mbar_expect_tx(my_mbar0 + k * 8, STAGE_BYTES);
                tma_half(my_buf0 + k * STAGE_BYTES, p, my_mbar0 + k * 8);
            }
        }
    }

    // ---- src row into registers (L2-hot); warp-local norm ----
    const float4* srcv = reinterpret_cast<const float4*>(src + (size_t)b * D_SZ);
    float4 sreg[8];
    float ss = 0.f;
    #pragma unroll
    for (int j = 0; j < 8; j++) {
        sreg[j] = __ldg(&srcv[j * 32 + lane]);
        ss += sreg[j].x * sreg[j].x + sreg[j].y * sreg[j].y
            + sreg[j].z * sreg[j].z + sreg[j].w * sreg[j].w;
    }
    #pragma unroll
    for (int o = 16; o > 0; o >>= 1) ss += __shfl_xor_sync(0xFFFFFFFFu, ss, o);
    const float inv_src = rsqrtf(fmaxf(ss, 1e-24f));

    float pos_acc = 0.f, neg_acc = 0.f, diag = 0.f;

    int hi = 0;
    for (int i = 0; i < nr; i++) {
        float dot = 0.f, rss = 0.f;

        #pragma unroll
        for (int h = 0; h < 2; h++, hi++) {
            const int q = hi / DEPTH;
            const int k = hi - q * DEPTH;

            mbar_wait(my_mbar0 + k * 8, (uint32_t)q & 1u);

            const float4* rv = reinterpret_cast<const float4*>(
                dsm + (size_t)(wid * DEPTH + k) * STAGE_BYTES);
            #pragma unroll
            for (int j = 0; j < 4; j++) {
                float4 v  = rv[j * 32 + lane];
                float4 sv = sreg[h * 4 + j];
                dot += v.x * sv.x + v.y * sv.y + v.z * sv.z + v.w * sv.w;
                rss += v.x * v.x + v.y * v.y + v.z * v.z + v.w * v.w;
            }

            // refill stage k with half hi+3 (all lanes of warp finished reading it)
            const int hn = hi + DEPTH;
            if (lane == 0 && hn < nh) {
                const float* p = row_ptr(tgt, rel, irr, b, first + (hn >> 1) * NWARPS)
                                 + (hn & 1) * (STAGE_BYTES / 4);
                mbar_expect_tx(my_mbar0 + k * 8, STAGE_BYTES);
                tma_half(my_buf0 + k * STAGE_BYTES, p, my_mbar0 + k * 8);
            }
        }

        // reduce while 2-3 half-stages stream underneath
        #pragma unroll
        for (int o = 16; o > 0; o >>= 1) {
            dot += __shfl_xor_sync(0xFFFFFFFFu, dot, o);
            rss += __shfl_xor_sync(0xFFFFFFFFu, rss, o);
        }
        if (lane == 0) {
            const int r = first + i * NWARPS;
            float c = dot * inv_src * rsqrtf(fmaxf(rss, 1e-24f));
            if (r == 0)            diag = c;
            else if (r <= P_SZ)    pos_acc += expf(c);
            else                   neg_acc += expf(c);
        }
    }

    if (lane == 0) { s_pos[wid] = pos_acc; s_neg[wid] = neg_acc; }
    __syncthreads();

    if (tid == 0) {
        g_pos[blk] = s_pos[0] + s_pos[1] + s_pos[2] + s_pos[3];
        g_neg[blk] = s_neg[0] + s_neg[1] + s_neg[2] + s_neg[3];
        if (s == 0) g_diag[b] = diag;   // block s=0, warp 0 owns row 0

        unsigned int old;
        asm volatile("atom.acq_rel.gpu.global.add.u32 %0, [%1], %2;"
                     : "=r"(old)
                     : "l"(&g_count), "r"(1u)
                     : "memory");
        s_last = (old == NBLOCKS - 1);
    }
    __syncthreads();

    // ---- last block computes the final loss (fused) ----
    if (s_last) {
        float acc = 0.f;
        #pragma unroll
        for (int it = 0; it < B_SZ / TPB; it++) {
            int bb = it * TPB + tid;
            float ps = 0.f, ns = 0.f;
            #pragma unroll
            for (int kk = 0; kk < SPLIT; kk++) {
                ps += g_pos[bb * SPLIT + kk];
                ns += g_neg[bb * SPLIT + kk];
            }
            float pos_score = 1.f + ps;
            float lp = logf(pos_score);
            float ln = logf(pos_score + ns);
            acc += -(ALPHA_F * g_diag[bb] + (1.f - ALPHA_F) * (lp - ln));
        }
        #pragma unroll
        for (int o = 16; o > 0; o >>= 1) acc += __shfl_xor_sync(0xFFFFFFFFu, acc, o);
        if (lane == 0) s_pos[wid] = acc;
        __syncthreads();
        if (tid == 0) {
            out[0] = (s_pos[0] + s_pos[1] + s_pos[2] + s_pos[3]) * (1.0f / (float)B_SZ);
            g_count = 0;                // reset for next graph replay
        }
    }
}

extern "C" void kernel_launch(void* const* d_in, const int* in_sizes, int n_in,
                              void* d_out, int out_size)
{
    const float* src = (const float*)d_in[0];   // [B, D]
    const float* tgt = (const float*)d_in[1];   // [B, D]
    const float* rel = (const float*)d_in[2];   // [B, P, D]
    const float* irr = (const float*)d_in[3];   // [B, N, D]
    float* out = (float*)d_out;

    cudaFuncSetAttribute(contrastive_loss_kernel,
                         cudaFuncAttributeMaxDynamicSharedMemorySize, SMEM_TOTAL);
    contrastive_loss_kernel<<<NBLOCKS, TPB, SMEM_TOTAL>>>(src, tgt, rel, irr, out);
}

// round 10
// speedup vs baseline: 1.1474x; 1.1474x over previous
#include <cuda_runtime.h>
#include <cstdint>

#define B_SZ 512
#define D_SZ 1024
#define P_SZ 16
#define N_SZ 128
#define ALPHA_F 0.8f
#define NROWS 145                 // row 0 = tgt, 1..16 = rel, 17..144 = irr
#define SPLIT 8
#define NBLOCKS (B_SZ * SPLIT)    // 4096
#define TPB 128
#define NWARPS 4
#define ROW_BYTES 4096            // 1024 fp32

__device__ float g_pos[NBLOCKS];
__device__ float g_neg[NBLOCKS];
__device__ float g_diag[B_SZ];
__device__ unsigned int g_count = 0;

__device__ __forceinline__ uint32_t smem_u32(const void* p) {
    uint32_t a;
    asm("{ .reg .u64 t; cvta.to.shared.u64 t, %1; cvt.u32.u64 %0, t; }"
        : "=r"(a) : "l"(p));
    return a;
}
__device__ __forceinline__ void mbar_init(uint32_t mbar, uint32_t count) {
    asm volatile("mbarrier.init.shared.b64 [%0], %1;" :: "r"(mbar), "r"(count) : "memory");
}
__device__ __forceinline__ void mbar_expect_tx(uint32_t mbar, uint32_t bytes) {
    asm volatile("mbarrier.arrive.expect_tx.shared.b64 _, [%0], %1;"
                 :: "r"(mbar), "r"(bytes) : "memory");
}
__device__ __forceinline__ void tma_row(uint32_t smem_dst, const float* gmem_src, uint32_t mbar) {
    asm volatile("cp.async.bulk.shared::cta.global.mbarrier::complete_tx::bytes "
                 "[%0], [%1], %2, [%3];"
                 :: "r"(smem_dst), "l"(gmem_src), "r"((uint32_t)ROW_BYTES), "r"(mbar)
                 : "memory");
}
__device__ __forceinline__ void mbar_wait(uint32_t mbar, uint32_t parity) {
    uint32_t done;
    asm volatile(
        "{\n\t.reg .pred p;\n\t"
        "mbarrier.try_wait.parity.acquire.cta.shared::cta.b64 p, [%1], %2;\n\t"
        "selp.b32 %0, 1, 0, p;\n\t}"
        : "=r"(done) : "r"(mbar), "r"(parity) : "memory");
    if (!done) {
        asm volatile(
            "{\n\t.reg .pred P1;\n\t"
            "W_%=:\n\t"
            "mbarrier.try_wait.parity.acquire.cta.shared::cta.b64 P1, [%0], %1, 0x989680;\n\t"
            "@P1 bra.uni D_%=;\n\t"
            "bra.uni W_%=;\n\t"
            "D_%=:\n\t}"
            :: "r"(mbar), "r"(parity) : "memory");
    }
}

__device__ __forceinline__ const float*
row_ptr(const float* __restrict__ tgt, const float* __restrict__ rel,
        const float* __restrict__ irr, int b, int r)
{
    if (r == 0)         return tgt + (size_t)b * D_SZ;
    else if (r <= P_SZ) return rel + ((size_t)b * P_SZ + (r - 1)) * D_SZ;
    else                return irr + ((size_t)b * N_SZ + (r - 1 - P_SZ)) * D_SZ;
}

__global__ void __launch_bounds__(TPB)
contrastive_loss_kernel(const float* __restrict__ src,
                        const float* __restrict__ tgt,
                        const float* __restrict__ rel,
                        const float* __restrict__ irr,
                        float* __restrict__ out)
{
    __shared__ __align__(16) float4 s_buf[NWARPS][2][ROW_BYTES / 16]; // 32 KB
    __shared__ __align__(8)  unsigned long long s_mbar[NWARPS][2];
    __shared__ float s_pos[NWARPS], s_neg[NWARPS];
    __shared__ int   s_last;

    const int blk  = blockIdx.x;
    const int b    = blk >> 3;            // batch row
    const int s    = blk & 7;             // split index
    const int tid  = threadIdx.x;
    const int wid  = tid >> 5;
    const int lane = tid & 31;

    const uint32_t mb0 = smem_u32(&s_mbar[wid][0]);
    const uint32_t mb1 = smem_u32(&s_mbar[wid][1]);
    const uint32_t sb0 = smem_u32(&s_buf[wid][0][0]);
    const uint32_t sb1 = smem_u32(&s_buf[wid][1][0]);

    // ---- per-warp mbarrier init ----
    if (lane == 0) {
        mbar_init(mb0, 1);
        mbar_init(mb1, 1);
        asm volatile("fence.mbarrier_init.release.cluster;" ::: "memory");
    }
    __syncwarp();

    // ---- rows for this warp: first, first+4, ... (R6 stride interleave) ----
    const int r0 = (s * NROWS) / SPLIT;
    const int r1 = ((s + 1) * NROWS) / SPLIT;
    const int first = r0 + wid;
    const int nr = (first < r1) ? ((r1 - first + NWARPS - 1) / NWARPS) : 0;

    // ---- prime the TMA pipeline (depth 2) before touching src ----
    if (lane == 0) {
        if (nr > 0) {
            mbar_expect_tx(mb0, ROW_BYTES);
            tma_row(sb0, row_ptr(tgt, rel, irr, b, first), mb0);
        }
        if (nr > 1) {
            mbar_expect_tx(mb1, ROW_BYTES);
            tma_row(sb1, row_ptr(tgt, rel, irr, b, first + NWARPS), mb1);
        }
    }

    // ---- src row into registers (L2-hot); warp-local norm ----
    const float4* srcv = reinterpret_cast<const float4*>(src + (size_t)b * D_SZ);
    float4 sreg[8];
    float ss = 0.f;
    #pragma unroll
    for (int j = 0; j < 8; j++) {
        sreg[j] = __ldg(&srcv[j * 32 + lane]);
        ss += sreg[j].x * sreg[j].x + sreg[j].y * sreg[j].y
            + sreg[j].z * sreg[j].z + sreg[j].w * sreg[j].w;
    }
    #pragma unroll
    for (int o = 16; o > 0; o >>= 1) ss += __shfl_xor_sync(0xFFFFFFFFu, ss, o);
    const float inv_src = rsqrtf(fmaxf(ss, 1e-24f));

    float pos_acc = 0.f, neg_acc = 0.f, diag = 0.f;

    uint32_t ph0 = 0, ph1 = 0;

    // ---- paired row loop: one butterfly window per TWO rows ----
    int i = 0;
    for (; i + 1 < nr; i += 2) {
        // row i (buffer 0)
        mbar_wait(mb0, ph0); ph0 ^= 1u;
        float dot0 = 0.f, rss0 = 0.f;
        {
            const float4* rv = &s_buf[wid][0][0];
            #pragma unroll
            for (int j = 0; j < 8; j++) {
                float4 v = rv[j * 32 + lane];
                dot0 += v.x * sreg[j].x + v.y * sreg[j].y + v.z * sreg[j].z + v.w * sreg[j].w;
                rss0 += v.x * v.x + v.y * v.y + v.z * v.z + v.w * v.w;
            }
        }
        if (lane == 0 && i + 2 < nr) {
            mbar_expect_tx(mb0, ROW_BYTES);
            tma_row(sb0, row_ptr(tgt, rel, irr, b, first + (i + 2) * NWARPS), mb0);
        }

        // row i+1 (buffer 1)
        mbar_wait(mb1, ph1); ph1 ^= 1u;
        float dot1 = 0.f, rss1 = 0.f;
        {
            const float4* rv = &s_buf[wid][1][0];
            #pragma unroll
            for (int j = 0; j < 8; j++) {
                float4 v = rv[j * 32 + lane];
                dot1 += v.x * sreg[j].x + v.y * sreg[j].y + v.z * sreg[j].z + v.w * sreg[j].w;
                rss1 += v.x * v.x + v.y * v.y + v.z * v.z + v.w * v.w;
            }
        }
        if (lane == 0 && i + 3 < nr) {
            mbar_expect_tx(mb1, ROW_BYTES);
            tma_row(sb1, row_ptr(tgt, rel, irr, b, first + (i + 3) * NWARPS), mb1);
        }

        // 4 interleaved butterfly chains: one serial-latency window for 2 rows
        #pragma unroll
        for (int o = 16; o > 0; o >>= 1) {
            dot0 += __shfl_xor_sync(0xFFFFFFFFu, dot0, o);
            rss0 += __shfl_xor_sync(0xFFFFFFFFu, rss0, o);
            dot1 += __shfl_xor_sync(0xFFFFFFFFu, dot1, o);
            rss1 += __shfl_xor_sync(0xFFFFFFFFu, rss1, o);
        }
        if (lane == 0) {
            const int rA = first + i * NWARPS;
            const int rB = rA + NWARPS;
            float cA = dot0 * inv_src * rsqrtf(fmaxf(rss0, 1e-24f));
            float cB = dot1 * inv_src * rsqrtf(fmaxf(rss1, 1e-24f));
            if (rA == 0)            diag = cA;
            else if (rA <= P_SZ)    pos_acc += __expf(cA);
            else                    neg_acc += __expf(cA);
            if (rB <= P_SZ)         pos_acc += __expf(cB);   // rB >= 4 always
            else                    neg_acc += __expf(cB);
        }
    }

    // leftover single row (i even -> buffer 0)
    if (i < nr) {
        mbar_wait(mb0, ph0); ph0 ^= 1u;
        float dot = 0.f, rss = 0.f;
        const float4* rv = &s_buf[wid][0][0];
        #pragma unroll
        for (int j = 0; j < 8; j++) {
            float4 v = rv[j * 32 + lane];
            dot += v.x * sreg[j].x + v.y * sreg[j].y + v.z * sreg[j].z + v.w * sreg[j].w;
            rss += v.x * v.x + v.y * v.y + v.z * v.z + v.w * v.w;
        }
        #pragma unroll
        for (int o = 16; o > 0; o >>= 1) {
            dot += __shfl_xor_sync(0xFFFFFFFFu, dot, o);
            rss += __shfl_xor_sync(0xFFFFFFFFu, rss, o);
        }
        if (lane == 0) {
            const int r = first + i * NWARPS;
            float c = dot * inv_src * rsqrtf(fmaxf(rss, 1e-24f));
            if (r == 0)            diag = c;
            else if (r <= P_SZ)    pos_acc += __expf(c);
            else                   neg_acc += __expf(c);
        }
    }

    if (lane == 0) { s_pos[wid] = pos_acc; s_neg[wid] = neg_acc; }
    __syncthreads();

    if (tid == 0) {
        g_pos[blk] = s_pos[0] + s_pos[1] + s_pos[2] + s_pos[3];
        g_neg[blk] = s_neg[0] + s_neg[1] + s_neg[2] + s_neg[3];
        if (s == 0) g_diag[b] = diag;   // block s=0 warp 0 owns row 0; tid0 = its lane0

        unsigned int old;
        asm volatile("atom.acq_rel.gpu.global.add.u32 %0, [%1], %2;"
                     : "=r"(old)
                     : "l"(&g_count), "r"(1u)
                     : "memory");
        s_last = (old == NBLOCKS - 1);
    }
    __syncthreads();

    // ---- last block computes the final loss (fused) ----
    if (s_last) {
        float acc = 0.f;
        #pragma unroll
        for (int it = 0; it < B_SZ / TPB; it++) {
            int bb = it * TPB + tid;
            float ps = 0.f, ns = 0.f;
            #pragma unroll
            for (int kk = 0; kk < SPLIT; kk++) {
                ps += g_pos[bb * SPLIT + kk];
                ns += g_neg[bb * SPLIT + kk];
            }
            float pos_score = 1.f + ps;
            float lp = __logf(pos_score);
            float ln = __logf(pos_score + ns);
            acc += -(ALPHA_F * g_diag[bb] + (1.f - ALPHA_F) * (lp - ln));
        }
        #pragma unroll
        for (int o = 16; o > 0; o >>= 1) acc += __shfl_xor_sync(0xFFFFFFFFu, acc, o);
        if (lane == 0) s_pos[wid] = acc;
        __syncthreads();
        if (tid == 0) {
            out[0] = (s_pos[0] + s_pos[1] + s_pos[2] + s_pos[3]) * (1.0f / (float)B_SZ);
            g_count = 0;                // reset for next graph replay
        }
    }
}

extern "C" void kernel_launch(void* const* d_in, const int* in_sizes, int n_in,
                              void* d_out, int out_size)
{
    const float* src = (const float*)d_in[0];   // [B, D]
    const float* tgt = (const float*)d_in[1];   // [B, D]
    const float* rel = (const float*)d_in[2];   // [B, P, D]
    const float* irr = (const float*)d_in[3];   // [B, N, D]
    float* out = (float*)d_out;

    contrastive_loss_kernel<<<NBLOCKS, TPB>>>(src, tgt, rel, irr, out);
}

// round 11
// speedup vs baseline: 1.1993x; 1.0452x over previous
#include <cuda_runtime.h>
#include <cstdint>

#define B_SZ 512
#define D_SZ 1024
#define P_SZ 16
#define N_SZ 128
#define ALPHA_F 0.8f
#define NROWS 145                       // per batch: row 0 = tgt, 1..16 = rel, 17..144 = irr
#define TOTAL_ROWS (B_SZ * NROWS)       // 74240
#define TPB 128
#define NWARPS 4
#define BLOCKS_PER_SM 6
#define ROW_BYTES 4096                  // 1024 fp32

__device__ float g_posb[B_SZ];          // zero-init at load; reset by last block each run
__device__ float g_negb[B_SZ];
__device__ float g_diag[B_SZ];
__device__ unsigned int g_count = 0;

__device__ __forceinline__ uint32_t smem_u32(const void* p) {
    uint32_t a;
    asm("{ .reg .u64 t; cvta.to.shared.u64 t, %1; cvt.u32.u64 %0, t; }"
        : "=r"(a) : "l"(p));
    return a;
}
__device__ __forceinline__ void mbar_init(uint32_t mbar, uint32_t count) {
    asm volatile("mbarrier.init.shared.b64 [%0], %1;" :: "r"(mbar), "r"(count) : "memory");
}
__device__ __forceinline__ void mbar_expect_tx(uint32_t mbar, uint32_t bytes) {
    asm volatile("mbarrier.arrive.expect_tx.shared.b64 _, [%0], %1;"
                 :: "r"(mbar), "r"(bytes) : "memory");
}
__device__ __forceinline__ void tma_row(uint32_t smem_dst, const float* gmem_src, uint32_t mbar) {
    asm volatile("cp.async.bulk.shared::cta.global.mbarrier::complete_tx::bytes "
                 "[%0], [%1], %2, [%3];"
                 :: "r"(smem_dst), "l"(gmem_src), "r"((uint32_t)ROW_BYTES), "r"(mbar)
                 : "memory");
}
__device__ __forceinline__ void mbar_wait(uint32_t mbar, uint32_t parity) {
    uint32_t done;
    asm volatile(
        "{\n\t.reg .pred p;\n\t"
        "mbarrier.try_wait.parity.acquire.cta.shared::cta.b64 p, [%1], %2;\n\t"
        "selp.b32 %0, 1, 0, p;\n\t}"
        : "=r"(done) : "r"(mbar), "r"(parity) : "memory");
    if (!done) {
        asm volatile(
            "{\n\t.reg .pred P1;\n\t"
            "W_%=:\n\t"
            "mbarrier.try_wait.parity.acquire.cta.shared::cta.b64 P1, [%0], %1, 0x989680;\n\t"
            "@P1 bra.uni D_%=;\n\t"
            "bra.uni W_%=;\n\t"
            "D_%=:\n\t}"
            :: "r"(mbar), "r"(parity) : "memory");
    }
}

// global row index -> gmem pointer (b = g / NROWS, r = g % NROWS)
__device__ __forceinline__ const float*
row_ptr_br(const float* __restrict__ tgt, const float* __restrict__ rel,
           const float* __restrict__ irr, int b, int r)
{
    if (r == 0)         return tgt + (size_t)b * D_SZ;
    else if (r <= P_SZ) return rel + ((size_t)b * P_SZ + (r - 1)) * D_SZ;
    else                return irr + ((size_t)b * N_SZ + (r - 1 - P_SZ)) * D_SZ;
}

__device__ __forceinline__ void
load_sreg(const float* __restrict__ src, int b, int lane,
          float4 (&sreg)[8], float& inv_src)
{
    const float4* sv = reinterpret_cast<const float4*>(src + (size_t)b * D_SZ);
    float ss = 0.f;
    #pragma unroll
    for (int j = 0; j < 8; j++) {
        sreg[j] = __ldg(&sv[j * 32 + lane]);
        ss += sreg[j].x * sreg[j].x + sreg[j].y * sreg[j].y
            + sreg[j].z * sreg[j].z + sreg[j].w * sreg[j].w;
    }
    #pragma unroll
    for (int o = 16; o > 0; o >>= 1) ss += __shfl_xor_sync(0xFFFFFFFFu, ss, o);
    inv_src = rsqrtf(fmaxf(ss, 1e-24f));
}

__global__ void __launch_bounds__(TPB, BLOCKS_PER_SM)
contrastive_loss_kernel(const float* __restrict__ src,
                        const float* __restrict__ tgt,
                        const float* __restrict__ rel,
                        const float* __restrict__ irr,
                        float* __restrict__ out,
                        int nblocks)
{
    __shared__ __align__(16) float4 s_buf[NWARPS][2][ROW_BYTES / 16]; // 32 KB
    __shared__ __align__(8)  unsigned long long s_mbar[NWARPS][2];
    __shared__ float s_red[NWARPS];
    __shared__ int   s_last;

    const int tid  = threadIdx.x;
    const int wid  = tid >> 5;
    const int lane = tid & 31;

    const uint32_t mb0 = smem_u32(&s_mbar[wid][0]);
    const uint32_t mb1 = smem_u32(&s_mbar[wid][1]);
    const uint32_t sb0 = smem_u32(&s_buf[wid][0][0]);
    const uint32_t sb1 = smem_u32(&s_buf[wid][1][0]);

    if (lane == 0) {
        mbar_init(mb0, 1);
        mbar_init(mb1, 1);
        asm volatile("fence.mbarrier_init.release.cluster;" ::: "memory");
    }
    __syncwarp();

    // ---- contiguous slice of the flat row space for this warp ----
    const int nw   = nblocks * NWARPS;
    const int wgid = blockIdx.x * NWARPS + wid;
    const int lo = (int)(((long long)wgid * TOTAL_ROWS) / nw);
    const int hi = (int)(((long long)(wgid + 1) * TOTAL_ROWS) / nw);

    // ---- prime pipeline once for the whole slice ----
    if (lane == 0) {
        if (lo < hi) {
            int pb = lo / NROWS, pr = lo - pb * NROWS;
            mbar_expect_tx(mb0, ROW_BYTES);
            tma_row(sb0, row_ptr_br(tgt, rel, irr, pb, pr), mb0);
        }
        if (lo + 1 < hi) {
            int pb = (lo + 1) / NROWS, pr = (lo + 1) - pb * NROWS;
            mbar_expect_tx(mb1, ROW_BYTES);
            tma_row(sb1, row_ptr_br(tgt, rel, irr, pb, pr), mb1);
        }
    }

    int b = lo / NROWS;
    int r = lo - b * NROWS;
    float4 sreg[8];
    float inv_src;
    load_sreg(src, b, lane, sreg, inv_src);

    float pos = 0.f, neg = 0.f;
    uint32_t ph0 = 0, ph1 = 0;

    for (int g = lo; g < hi; g++) {
        if (r == NROWS) {              // crossed into next batch row
            if (lane == 0) {
                atomicAdd(&g_posb[b], pos);
                atomicAdd(&g_negb[b], neg);
                pos = 0.f; neg = 0.f;
            }
            b++; r = 0;
            load_sreg(src, b, lane, sreg, inv_src);
        }

        const int k = (g - lo) & 1;
        if (k == 0) { mbar_wait(mb0, ph0); ph0 ^= 1u; }
        else        { mbar_wait(mb1, ph1); ph1 ^= 1u; }

        const float4* rv = &s_buf[wid][k][0];
        float dot = 0.f, rss = 0.f;
        #pragma unroll
        for (int j = 0; j < 8; j++) {
            float4 v = rv[j * 32 + lane];
            dot += v.x * sreg[j].x + v.y * sreg[j].y + v.z * sreg[j].z + v.w * sreg[j].w;
            rss += v.x * v.x + v.y * v.y + v.z * v.z + v.w * v.w;
        }

        // refill this stage with row g+2 (all lanes finished reading it)
        if (lane == 0 && g + 2 < hi) {
            int r2 = r + 2, b2 = b;
            if (r2 >= NROWS) { r2 -= NROWS; b2++; }
            const uint32_t mb = k ? mb1 : mb0;
            const uint32_t sb = k ? sb1 : sb0;
            mbar_expect_tx(mb, ROW_BYTES);
            tma_row(sb, row_ptr_br(tgt, rel, irr, b2, r2), mb);
        }

        #pragma unroll
        for (int o = 16; o > 0; o >>= 1) {
            dot += __shfl_xor_sync(0xFFFFFFFFu, dot, o);
            rss += __shfl_xor_sync(0xFFFFFFFFu, rss, o);
        }
        if (lane == 0) {
            float c = dot * inv_src * rsqrtf(fmaxf(rss, 1e-24f));
            if (r == 0)            g_diag[b] = c;          // tgt row: diag
            else if (r <= P_SZ)    pos += __expf(c);
            else                   neg += __expf(c);
        }
        r++;
    }

    if (lane == 0) {
        atomicAdd(&g_posb[b], pos);
        atomicAdd(&g_negb[b], neg);
    }
    __syncthreads();

    if (tid == 0) {
        unsigned int old;
        asm volatile("atom.acq_rel.gpu.global.add.u32 %0, [%1], %2;"
                     : "=r"(old)
                     : "l"(&g_count), "r"(1u)
                     : "memory");
        s_last = (old == (unsigned)nblocks - 1u);
    }
    __syncthreads();

    // ---- last block: final loss over 512 batch rows + reset accumulators ----
    if (s_last) {
        float acc = 0.f;
        #pragma unroll
        for (int it = 0; it < B_SZ / TPB; it++) {
            int bb = it * TPB + tid;
            float ps = __ldcg(&g_posb[bb]);
            float ns = __ldcg(&g_negb[bb]);
            float dg = __ldcg(&g_diag[bb]);
            float pos_score = 1.f + ps;
            float lp = __logf(pos_score);
            float ln = __logf(pos_score + ns);
            acc += -(ALPHA_F * dg + (1.f - ALPHA_F) * (lp - ln));
            g_posb[bb] = 0.f;          // reset for next graph replay
            g_negb[bb] = 0.f;
        }
        #pragma unroll
        for (int o = 16; o > 0; o >>= 1) acc += __shfl_xor_sync(0xFFFFFFFFu, acc, o);
        if (lane == 0) s_red[wid] = acc;
        __syncthreads();
        if (tid == 0) {
            out[0] = (s_red[0] + s_red[1] + s_red[2] + s_red[3]) * (1.0f / (float)B_SZ);
            g_count = 0;
        }
    }
}

extern "C" void kernel_launch(void* const* d_in, const int* in_sizes, int n_in,
                              void* d_out, int out_size)
{
    const float* src = (const float*)d_in[0];   // [B, D]
    const float* tgt = (const float*)d_in[1];   // [B, D]
    const float* rel = (const float*)d_in[2];   // [B, P, D]
    const float* irr = (const float*)d_in[3];   // [B, N, D]
    float* out = (float*)d_out;

    int sms = 148;
    cudaDeviceGetAttribute(&sms, cudaDevAttrMultiProcessorCount, 0);
    const int nblocks = sms * BLOCKS_PER_SM;    // exactly one wave

    contrastive_loss_kernel<<<nblocks, TPB>>>(src, tgt, rel, irr, out, nblocks);
}